// round 11
// baseline (speedup 1.0000x reference)
#include <cuda_runtime.h>
#include <cuda_bf16.h>
#include <cuda_fp16.h>
#include <math.h>
#include <cstdint>

// Shapes (fixed)
#define DIMN   1024
#define BB     2
#define TT     512
#define HH     8
#define HKD    128
#define NROWS  (BB*TT)          // 1024
#define CH     64               // chunk length
#define NC     (TT/CH)          // 8 chunks
#define QSCALE 0.08838834764831845f   // 128^-0.5
#define GNORM  0.0625f                // 1/16

// ---------------------------------------------------------------------------
// Scratch (no cudaMalloc allowed)
// ---------------------------------------------------------------------------
__device__ float g_q [NROWS*DIMN];
__device__ float g_k [NROWS*DIMN];
__device__ float g_v [NROWS*DIMN];
__device__ float g_g [NROWS*DIMN];
__device__ float g_gk[NROWS*DIMN];
// chunked-GLA scratch
__device__ float g_qg[NROWS*DIMN];
__device__ float g_kd[NROWS*DIMN];
__device__ float g_kv[16*NC*HKD*HKD];
__device__ float g_S [16*NC*HKD*HKD];
__device__ float g_dc[16*NC*HKD];
// fp16 split-2 operands: A = Ah + Al (fp16), W = Wh (fp16; Wl dropped)
__device__ __half g_xh [NROWS*DIMN];
__device__ __half g_xl [NROWS*DIMN];
__device__ __half g_onh[NROWS*DIMN];
__device__ __half g_onl[NROWS*DIMN];
__device__ __half g_Wh [5*DIMN*DIMN];   // transposed: [n][k]

// ---------------------------------------------------------------------------
// PTX helpers (all non-'a'-gated: cp.async / ldmatrix / mma.sync)
// ---------------------------------------------------------------------------
__device__ __forceinline__ uint32_t smem_u32(const void* p) {
    uint32_t a;
    asm("{ .reg .u64 t; cvta.to.shared.u64 t, %1; cvt.u32.u64 %0, t; }"
        : "=r"(a) : "l"(p));
    return a;
}
__device__ __forceinline__ void cp16(uint32_t dst, const void* src) {
    asm volatile("cp.async.cg.shared.global [%0], [%1], 16;"
                 :: "r"(dst), "l"(src) : "memory");
}
__device__ __forceinline__ void cp_commit() {
    asm volatile("cp.async.commit_group;" ::: "memory");
}
__device__ __forceinline__ void ldsm4(uint32_t& r0, uint32_t& r1,
                                      uint32_t& r2, uint32_t& r3, uint32_t a) {
    asm volatile("ldmatrix.sync.aligned.m8n8.x4.shared.b16 {%0,%1,%2,%3}, [%4];"
                 : "=r"(r0), "=r"(r1), "=r"(r2), "=r"(r3) : "r"(a));
}
__device__ __forceinline__ void mma16816h(float* c, const uint32_t* a,
                                          const uint32_t* b) {
    asm volatile("mma.sync.aligned.m16n8k16.row.col.f32.f16.f16.f32 "
        "{%0,%1,%2,%3}, {%4,%5,%6,%7}, {%8,%9}, {%0,%1,%2,%3};"
        : "+f"(c[0]), "+f"(c[1]), "+f"(c[2]), "+f"(c[3])
        : "r"(a[0]), "r"(a[1]), "r"(a[2]), "r"(a[3]), "r"(b[0]), "r"(b[1]));
}

__device__ __forceinline__ void split_fp16(float x, __half& h, __half& l) {
    h = __float2half(x);
    l = __float2half(x - __half2float(h));
}

// ---------------------------------------------------------------------------
// Prelude kernel: conv_w (5120 blocks) + conv_x (1024) + lowrank_gk (64)
// merged via blockIdx range split so they co-schedule in one launch.
// Device globals referenced INSIDE (ATS shadow pitfall).
// ---------------------------------------------------------------------------
__global__ __launch_bounds__(256) void prelude_kernel(
    const float* __restrict__ x,
    const float* __restrict__ Wq, const float* __restrict__ Wk,
    const float* __restrict__ Wv, const float* __restrict__ Wg,
    const float* __restrict__ Wo,
    const float* __restrict__ Wgk1, const float* __restrict__ Wgk2,
    const float* __restrict__ bgk2)
{
    __shared__ float sbuf[5376];        // union: conv_w 1056 / lowrank 5376
    const int bid = blockIdx.x;
    const int tid = threadIdx.x;

    if (bid < 5120) {
        // ---- conv_w: W fp32 [k][n] -> transposed fp16 Wh [n][k] ----
        const float* Ws[5] = {Wq, Wk, Wv, Wg, Wo};
        const int z   = bid >> 10;
        const int rem = bid & 1023;
        const int kt0 = (rem >> 5) * 32;
        const int nt0 = (rem & 31) * 32;
        const float* W = Ws[z];
        __half* Dh = g_Wh + (size_t)z * DIMN * DIMN;

        float (*s)[33] = (float(*)[33])sbuf;
        int tx = tid & 31, ty = tid >> 5;
#pragma unroll
        for (int j = 0; j < 4; j++)
            s[ty + j*8][tx] = W[(kt0 + ty + j*8) * DIMN + nt0 + tx];
        __syncthreads();
#pragma unroll
        for (int j = 0; j < 4; j++) {
            int n = nt0 + ty + j*8, k = kt0 + tx;
            Dh[(size_t)n * DIMN + k] = __float2half(s[tx][ty + j*8]);
        }
    } else if (bid < 6144) {
        // ---- conv_x: x fp32 -> xh + xl fp16 ----
        int i = (bid - 5120) * 256 + tid;        // float4 index
        float4 v = ((const float4*)x)[i];
        union { __half h[4]; uint2 u; } hh, ll;
        split_fp16(v.x, hh.h[0], ll.h[0]); split_fp16(v.y, hh.h[1], ll.h[1]);
        split_fp16(v.z, hh.h[2], ll.h[2]); split_fp16(v.w, hh.h[3], ll.h[3]);
        ((uint2*)g_xh)[i] = hh.u;
        ((uint2*)g_xl)[i] = ll.u;
    } else {
        // ---- lowrank_gk: 16 rows per block ----
        const int m0 = (bid - 6144) * 16;
        float (*sX)[64]       = (float(*)[64])sbuf;            // 1024
        float (*sPart)[16][16] = (float(*)[16][16])(sbuf + 1024); // 4096
        float (*sT1)[16]      = (float(*)[16])(sbuf + 5120);   // 256

        const int kk = tid >> 4;
        const int cc = tid & 15;

        float acc16[16];
#pragma unroll
        for (int r = 0; r < 16; r++) acc16[r] = 0.f;

        for (int kc = 0; kc < 16; kc++) {
            {
                int row = tid >> 4, c4 = (tid & 15) << 2;
                *(float4*)&sX[row][c4] =
                    *(const float4*)(x + (size_t)(m0 + row) * DIMN + kc * 64 + c4);
            }
            __syncthreads();
#pragma unroll
            for (int i = 0; i < 4; i++) {
                int k = kk * 4 + i;
                float w1 = Wgk1[(kc * 64 + k) * 16 + cc];
#pragma unroll
                for (int r = 0; r < 16; r++)
                    acc16[r] = fmaf(sX[r][k], w1, acc16[r]);
            }
            __syncthreads();
        }
#pragma unroll
        for (int r = 0; r < 16; r++) sPart[kk][r][cc] = acc16[r];
        __syncthreads();

        {
            int rr = tid >> 4;
            float s = 0.f;
#pragma unroll
            for (int j = 0; j < 16; j++) s += sPart[j][rr][cc];
            sT1[rr][cc] = s;
        }
        __syncthreads();

#pragma unroll
        for (int u = 0; u < 4; u++) {
            int n = u * 256 + tid;
            float w2[16];
#pragma unroll
            for (int j = 0; j < 16; j++) w2[j] = Wgk2[j * DIMN + n];
            float bias = bgk2[n];
#pragma unroll
            for (int r = 0; r < 16; r++) {
                float a = bias;
#pragma unroll
                for (int j = 0; j < 16; j++)
                    a = fmaf(sT1[r][j], w2[j], a);
                float ls = fminf(a, 0.f) - log1pf(__expf(-fabsf(a)));
                g_gk[(size_t)(m0 + r) * DIMN + n] = ls * GNORM;
            }
        }
    }
}

// ---------------------------------------------------------------------------
// HMMA fp16 split-2 GEMM: C[1024,1024] = alpha * A @ W
//   C = Ah@Wh + Al@Wh (Wl dropped; rel err ~2^-12.3).
//   Block tile 128x64, BK=32, 8 warps (4m x 2n), warp tile 32x32.
//   3-stage cp.async pipeline + register fragment double-buffering,
//   ONE __syncthreads per K-step.
// ---------------------------------------------------------------------------
#define STG_H  20480
#define O_AH   0
#define O_AL   8192
#define O_BH   16384
#define SMEM_GEMM (3*STG_H)     // 60 KB (opt-in attr; 2 blocks/SM)

__device__ __forceinline__ uint32_t sw_addr(uint32_t region, int row, int chunk) {
    return region + row * 64 + ((chunk ^ ((row >> 1) & 3)) << 4);
}

__device__ __forceinline__ void load_stage(
    uint32_t sb, int s,
    const __half* __restrict__ Ah, const __half* __restrict__ Al,
    const __half* __restrict__ Bh,
    int m0, int n0, int k0, int tid)
{
    uint32_t st = sb + s * STG_H;
#pragma unroll
    for (int i = 0; i < 2; i++) {
        int idx = tid + (i << 8);          // 0..511
        int row = idx >> 2, c = idx & 3;
        const size_t go = (size_t)(m0 + row) * DIMN + k0 + c * 8;
        cp16(sw_addr(st + O_AH, row, c), Ah + go);
        cp16(sw_addr(st + O_AL, row, c), Al + go);
    }
    {
        int row = tid >> 2, c = tid & 3;   // 64 rows x 4 chunks
        const size_t go = (size_t)(n0 + row) * DIMN + k0 + c * 8;
        cp16(sw_addr(st + O_BH, row, c), Bh + go);
    }
    cp_commit();
}

struct FragSet {
    uint32_t ah[2][4], al[2][4];
    uint32_t bh[4][2];
};

__device__ __forceinline__ void ld_frags(FragSet& f, uint32_t st, int ch,
                                         int wm0, int wn0, int lr)
{
#pragma unroll
    for (int mt = 0; mt < 2; mt++) {
        int row = wm0 + mt * 16 + lr;
        ldsm4(f.ah[mt][0], f.ah[mt][1], f.ah[mt][2], f.ah[mt][3],
              sw_addr(st + O_AH, row, ch));
        ldsm4(f.al[mt][0], f.al[mt][1], f.al[mt][2], f.al[mt][3],
              sw_addr(st + O_AL, row, ch));
    }
#pragma unroll
    for (int ng = 0; ng < 2; ng++) {
        int row = wn0 + ng * 16 + lr;
        uint32_t t0, t1, t2, t3;
        ldsm4(t0, t1, t2, t3, sw_addr(st + O_BH, row, ch));
        f.bh[ng*2][0] = t0; f.bh[ng*2+1][0] = t1;
        f.bh[ng*2][1] = t2; f.bh[ng*2+1][1] = t3;
    }
}

__device__ __forceinline__ void mma_set(float acc[2][4][4], const FragSet& f)
{
#pragma unroll
    for (int mt = 0; mt < 2; mt++)
#pragma unroll
        for (int nt = 0; nt < 4; nt++) {
            mma16816h(acc[mt][nt], f.ah[mt], f.bh[nt]);
            mma16816h(acc[mt][nt], f.al[mt], f.bh[nt]);
        }
}

__device__ __forceinline__ void gemm_body(
    const __half* __restrict__ Ah, const __half* __restrict__ Al,
    const __half* __restrict__ Bh,
    float* __restrict__ C, float alpha, char* smem)
{
    const int tid  = threadIdx.x;
    const int wid  = tid >> 5;
    const int lane = tid & 31;
    const int m0 = blockIdx.y * 128;
    const int n0 = blockIdx.x * 64;
    const int wm0 = (wid & 3) * 32;     // warp m within block
    const int wn0 = (wid >> 2) * 32;    // warp n within block
    const uint32_t sb = smem_u32(smem);

    float acc[2][4][4];
#pragma unroll
    for (int mt = 0; mt < 2; mt++)
#pragma unroll
        for (int nt = 0; nt < 4; nt++)
#pragma unroll
            for (int i = 0; i < 4; i++) acc[mt][nt][i] = 0.f;

    load_stage(sb, 0, Ah, Al, Bh, m0, n0, 0,  tid);
    load_stage(sb, 1, Ah, Al, Bh, m0, n0, 32, tid);

    const int lr = lane & 15;
    const int lc = lane >> 4;

    asm volatile("cp.async.wait_group 1;" ::: "memory");
    __syncthreads();

    FragSet cur, nxt;
    int stage = 0;
    uint32_t st = sb;
    ld_frags(cur, st, lc, wm0, wn0, lr);          // (kt=0, ks=0)

    for (int kt = 0; kt < 32; kt++) {
        ld_frags(nxt, st, 2 + lc, wm0, wn0, lr);  // (kt, ks=1)
        mma_set(acc, cur);                        // covers nxt's ldsm latency
        if (kt < 31) {
            if (kt < 30) {
                int ns = stage + 2; if (ns >= 3) ns -= 3;
                load_stage(sb, ns, Ah, Al, Bh, m0, n0, (kt + 2) * 32, tid);
                asm volatile("cp.async.wait_group 1;" ::: "memory");
            } else {
                asm volatile("cp.async.wait_group 0;" ::: "memory");
            }
            __syncthreads();
            stage++; if (stage == 3) stage = 0;
            st = sb + stage * STG_H;
            ld_frags(cur, st, lc, wm0, wn0, lr);  // (kt+1, ks=0)
        }
        mma_set(acc, nxt);                        // covers cur's ldsm latency
    }

    const int er = lane >> 2;
    const int ec = (lane & 3) << 1;
#pragma unroll
    for (int mt = 0; mt < 2; mt++)
#pragma unroll
        for (int nt = 0; nt < 4; nt++) {
            int row = m0 + wm0 + mt * 16 + er;
            int col = n0 + wn0 + nt * 8 + ec;
            float2 v0 = make_float2(acc[mt][nt][0] * alpha, acc[mt][nt][1] * alpha);
            float2 v1 = make_float2(acc[mt][nt][2] * alpha, acc[mt][nt][3] * alpha);
            *(float2*)(C + (size_t)row * DIMN + col)       = v0;
            *(float2*)(C + (size_t)(row + 8) * DIMN + col) = v1;
        }
}

__global__ __launch_bounds__(256, 2) void gemm4_kernel()
{
    extern __shared__ char smem[];
    const int z = blockIdx.z;
    const __half* Bh = g_Wh + (size_t)z * DIMN * DIMN;
    float* outs[4] = {g_q, g_k, g_v, g_g};
    float alpha = (z == 0) ? QSCALE : 1.f;
    gemm_body(g_xh, g_xl, Bh, outs[z], alpha, smem);
}

__global__ __launch_bounds__(256, 2) void gemmo_kernel(float* __restrict__ out)
{
    extern __shared__ char smem[];
    gemm_body(g_onh, g_onl, g_Wh + (size_t)4 * DIMN * DIMN, out, 1.f, smem);
}

// ---------------------------------------------------------------------------
// Chunked GLA
// ---------------------------------------------------------------------------
__device__ __forceinline__ int row_off(int b, int h, int t)
{
    return (((b * TT + t) * HH + h) << 7);
}

// Fused prep + chunk_kv, 512 threads: 4-segment gate prefix, then KV matmul
// with 4k x 8v per thread. k~ stays in smem.
__global__ __launch_bounds__(512) void prep_kv_kernel()
{
    const int bhc = blockIdx.x;
    const int bh  = bhc >> 3, c0 = bhc & 7;
    const int b   = bh >> 3,  h  = bh & 7;
    const int tid = threadIdx.x;
    const int ch  = tid & 127;
    const int tg  = tid >> 7;          // 0..3, each handles 16 t's
    const int tb  = c0 * CH + tg * 16;

    __shared__ float gsum[4][128];
    __shared__ float sK[64][128];      // k~ [t][channel], 32 KB
    __shared__ float sV[16][128];

    float loc[16];
    {
        float a = 0.f;
#pragma unroll
        for (int s = 0; s < 16; s++) {
            loc[s] = g_gk[row_off(b, h, tb + s) + ch];
            a += loc[s];
        }
        gsum[tg][ch] = a;
    }
    __syncthreads();
    {
        float off = 0.f;
#pragma unroll
        for (int g = 0; g < 4; g++)
            if (g < tg) off += gsum[g][ch];
        float tot = gsum[0][ch] + gsum[1][ch] + gsum[2][ch] + gsum[3][ch];
        float bacc = off;
#pragma unroll 4
        for (int s = 0; s < 16; s++) {
            bacc += loc[s];
            int r = row_off(b, h, tb + s) + ch;
            float q = g_q[r], k = g_k[r];
            g_qg[r] = q * __expf(bacc);
            g_kd[r] = k * __expf(-bacc);
            sK[tg * 16 + s][ch] = k * __expf(tot - bacc);
        }
        if (tg == 0) g_dc[bhc * 128 + ch] = __expf(tot);
    }
    __syncthreads();

    // KV matmul: contraction over s=64, output [k 128][v 128], 4x8 per thread
    const int tr  = tid >> 4, tc = tid & 15;   // tr 0..31
    const int kr0 = tr << 2, vc0 = tc << 3;
    const int tbase = c0 * CH;

    float acc[4][8];
#pragma unroll
    for (int i = 0; i < 4; i++)
#pragma unroll
        for (int j = 0; j < 8; j++) acc[i][j] = 0.f;

    for (int st = 0; st < 4; st++) {
        {
            int sr = tid >> 5;
            int sc = (tid & 31) << 2;
            int r  = row_off(b, h, tbase + st * 16 + sr) + sc;
            *(float4*)&sV[sr][sc] = *(const float4*)(g_v + r);
        }
        __syncthreads();
#pragma unroll
        for (int ss = 0; ss < 16; ss++) {
            int s = st * 16 + ss;
            float4 k4 = *(const float4*)&sK[s][kr0];
            float4 v0 = *(const float4*)&sV[ss][vc0];
            float4 v1 = *(const float4*)&sV[ss][vc0 + 4];
            float kr[4] = {k4.x,k4.y,k4.z,k4.w};
            float vr[8] = {v0.x,v0.y,v0.z,v0.w,v1.x,v1.y,v1.z,v1.w};
#pragma unroll
            for (int i = 0; i < 4; i++)
#pragma unroll
                for (int j = 0; j < 8; j++)
                    acc[i][j] = fmaf(kr[i], vr[j], acc[i][j]);
        }
        __syncthreads();
    }

    float* dst = g_kv + (size_t)bhc * 16384;
#pragma unroll
    for (int i = 0; i < 4; i++) {
        *(float4*)(dst + (kr0 + i) * 128 + vc0)     = make_float4(acc[i][0],acc[i][1],acc[i][2],acc[i][3]);
        *(float4*)(dst + (kr0 + i) * 128 + vc0 + 4) = make_float4(acc[i][4],acc[i][5],acc[i][6],acc[i][7]);
    }
}

// state scan: parallel over (bh, v-group of 16); serial over 8 chunks.
__global__ __launch_bounds__(256) void state_scan_kernel()
{
    const int bh = blockIdx.x >> 3;
    const int vg = blockIdx.x & 7;
    const int tid = threadIdx.x;
    const int k    = tid >> 1;
    const int voff = vg * 16 + (tid & 1) * 8;

    float4 S0 = make_float4(0.f,0.f,0.f,0.f);
    float4 S1 = make_float4(0.f,0.f,0.f,0.f);

    for (int c = 0; c < NC; c++) {
        const int bhc = bh * NC + c;
        const size_t base = (size_t)bhc * 16384 + (size_t)k * 128 + voff;
        const float d = g_dc[bhc * 128 + k];
        *(float4*)(g_S + base)     = S0;
        *(float4*)(g_S + base + 4) = S1;
        float4 a = *(const float4*)(g_kv + base);
        float4 b = *(const float4*)(g_kv + base + 4);
        S0.x = fmaf(S0.x, d, a.x); S0.y = fmaf(S0.y, d, a.y);
        S0.z = fmaf(S0.z, d, a.z); S0.w = fmaf(S0.w, d, a.w);
        S1.x = fmaf(S1.x, d, b.x); S1.y = fmaf(S1.y, d, b.y);
        S1.z = fmaf(S1.z, d, b.z); S1.w = fmaf(S1.w, d, b.w);
    }
}

// chunk_out: o = q~ @ S_c + tril(q~ @ k^^T) @ V, fused gated RMSNorm,
// writes fp16 hi/lo splits directly (feeds gemmo).
__global__ __launch_bounds__(256) void chunk_out_kernel(
    const float* __restrict__ g_norm_w)
{
    const int bhc = blockIdx.x;
    const int bh  = bhc >> 3, c0 = bhc & 7;
    const int b   = bh >> 3,  h  = bh & 7;
    const int tid = threadIdx.x;
    const int tr  = tid >> 4, tc = tid & 15;
    const int t0  = tr << 2;
    const int v0  = tc << 3;
    const int tbase = c0 * CH;

    __shared__ float sQ [16][68];
    __shared__ float sKd[16][68];
    __shared__ float sS [16][128];
    __shared__ float sA [64][68];
    __shared__ float sV [16][128];

    float o[4][8];
    float a2[4][4];
#pragma unroll
    for (int i = 0; i < 4; i++) {
#pragma unroll
        for (int j = 0; j < 8; j++) o[i][j] = 0.f;
#pragma unroll
        for (int j = 0; j < 4; j++) a2[i][j] = 0.f;
    }

    const size_t Sbase = (size_t)bhc * 16384;

    for (int k0 = 0; k0 < 128; k0 += 16) {
        {
            int tt = tid >> 2;
            int c4 = (tid & 3) << 2;
            int r  = row_off(b, h, tbase + tt) + k0 + c4;
            float4 qv = *(const float4*)(g_qg + r);
            sQ[c4+0][tt] = qv.x; sQ[c4+1][tt] = qv.y;
            sQ[c4+2][tt] = qv.z; sQ[c4+3][tt] = qv.w;
            float4 kv = *(const float4*)(g_kd + r);
            sKd[c4+0][tt] = kv.x; sKd[c4+1][tt] = kv.y;
            sKd[c4+2][tt] = kv.z; sKd[c4+3][tt] = kv.w;
        }
#pragma unroll
        for (int u = 0; u < 2; u++) {
            int f  = tid + (u << 8);
            int sr = f >> 5;
            int sc = (f & 31) << 2;
            *(float4*)&sS[sr][sc] =
                *(const float4*)(g_S + Sbase + (k0 + sr) * 128 + sc);
        }
        __syncthreads();

#pragma unroll
        for (int kk = 0; kk < 16; kk++) {
            float4 q4  = *(const float4*)&sQ[kk][t0];
            float4 s0  = *(const float4*)&sS[kk][v0];
            float4 s1  = *(const float4*)&sS[kk][v0 + 4];
            float4 kd4 = *(const float4*)&sKd[kk][tc << 2];
            float qr[4] = {q4.x, q4.y, q4.z, q4.w};
            float sr_[8] = {s0.x,s0.y,s0.z,s0.w,s1.x,s1.y,s1.z,s1.w};
            float kr[4] = {kd4.x,kd4.y,kd4.z,kd4.w};
#pragma unroll
            for (int i = 0; i < 4; i++) {
#pragma unroll
                for (int j = 0; j < 8; j++)
                    o[i][j] = fmaf(qr[i], sr_[j], o[i][j]);
#pragma unroll
                for (int j = 0; j < 4; j++)
                    a2[i][j] = fmaf(qr[i], kr[j], a2[i][j]);
            }
        }
        __syncthreads();
    }

#pragma unroll
    for (int i = 0; i < 4; i++) {
        int t = t0 + i;
#pragma unroll
        for (int j = 0; j < 4; j++) {
            int s = (tc << 2) + j;
            sA[t][s] = (s <= t) ? a2[i][j] : 0.f;
        }
    }
    __syncthreads();

    for (int st = 0; st < 4; st++) {
#pragma unroll
        for (int u = 0; u < 2; u++) {
            int f  = tid + (u << 8);
            int sr = f >> 5;
            int sc = (f & 31) << 2;
            int r  = row_off(b, h, tbase + st * 16 + sr) + sc;
            *(float4*)&sV[sr][sc] = *(const float4*)(g_v + r);
        }
        __syncthreads();
#pragma unroll
        for (int ss = 0; ss < 16; ss++) {
            int s = st * 16 + ss;
            float a[4];
#pragma unroll
            for (int i = 0; i < 4; i++) a[i] = sA[t0 + i][s];
            float4 vv0 = *(const float4*)&sV[ss][v0];
            float4 vv1 = *(const float4*)&sV[ss][v0 + 4];
            float vr[8] = {vv0.x,vv0.y,vv0.z,vv0.w,vv1.x,vv1.y,vv1.z,vv1.w};
#pragma unroll
            for (int i = 0; i < 4; i++)
#pragma unroll
                for (int j = 0; j < 8; j++)
                    o[i][j] = fmaf(a[i], vr[j], o[i][j]);
        }
        __syncthreads();
    }

    float4 w0 = *(const float4*)(g_norm_w + v0);
    float4 w1 = *(const float4*)(g_norm_w + v0 + 4);
    float wr[8] = {w0.x,w0.y,w0.z,w0.w,w1.x,w1.y,w1.z,w1.w};

#pragma unroll
    for (int i = 0; i < 4; i++) {
        float ss = 0.f;
#pragma unroll
        for (int j = 0; j < 8; j++) ss = fmaf(o[i][j], o[i][j], ss);
#pragma unroll
        for (int off = 1; off < 16; off <<= 1)
            ss += __shfl_xor_sync(0xffffffffu, ss, off);
        float rms = rsqrtf(ss * (1.f / 128.f) + 1e-5f);

        int r = row_off(b, h, tbase + t0 + i);
        float4 gg0 = *(const float4*)(g_g + r + v0);
        float4 gg1 = *(const float4*)(g_g + r + v0 + 4);
        float gr[8] = {gg0.x,gg0.y,gg0.z,gg0.w,gg1.x,gg1.y,gg1.z,gg1.w};

        union { __half h[8]; uint4 u; } hh;
        union { __half h[8]; uint4 u; } ll;
#pragma unroll
        for (int j = 0; j < 8; j++) {
            float gvv = gr[j];
            float sw  = gvv / (1.f + __expf(-gvv));
            float on  = o[i][j] * rms * wr[j] * sw;
            split_fp16(on, hh.h[j], ll.h[j]);
        }
        *(uint4*)&g_onh[r + v0] = hh.u;
        *(uint4*)&g_onl[r + v0] = ll.u;
    }
}

// ---------------------------------------------------------------------------
extern "C" void kernel_launch(void* const* d_in, const int* in_sizes, int n_in,
                              void* d_out, int out_size)
{
    const float* x        = (const float*)d_in[0];
    const float* Wq       = (const float*)d_in[1];
    const float* Wk       = (const float*)d_in[2];
    const float* Wv       = (const float*)d_in[3];
    const float* Wg       = (const float*)d_in[4];
    const float* Wgk1     = (const float*)d_in[5];
    const float* Wgk2     = (const float*)d_in[6];
    const float* bgk2     = (const float*)d_in[7];
    const float* g_norm_w = (const float*)d_in[8];
    const float* Wo       = (const float*)d_in[9];
    float* out = (float*)d_out;

    // Host-side attribute set; executed during capture, not a graph node.
    cudaFuncSetAttribute(gemm4_kernel,
        cudaFuncAttributeMaxDynamicSharedMemorySize, SMEM_GEMM);
    cudaFuncSetAttribute(gemmo_kernel,
        cudaFuncAttributeMaxDynamicSharedMemorySize, SMEM_GEMM);

    prelude_kernel<<<6208, 256>>>(x, Wq, Wk, Wv, Wg, Wo, Wgk1, Wgk2, bgk2);
    gemm4_kernel<<<dim3(16, 8, 4), 256, SMEM_GEMM>>>();
    prep_kv_kernel<<<128, 512>>>();
    state_scan_kernel<<<128, 256>>>();
    chunk_out_kernel<<<128, 256>>>(g_norm_w);
    gemmo_kernel<<<dim3(16, 8), 256, SMEM_GEMM>>>(out);
}

// round 12
// speedup vs baseline: 1.1644x; 1.1644x over previous
#include <cuda_runtime.h>
#include <cuda_bf16.h>
#include <math.h>
#include <cstdint>

// Shapes (fixed)
#define DIMN   1024
#define BB     2
#define TT     512
#define HH     8
#define HKD    128
#define NROWS  (BB*TT)          // 1024
#define CH     64               // chunk length
#define NC     (TT/CH)          // 8 chunks
#define QSCALE 0.08838834764831845f   // 128^-0.5
#define GNORM  0.0625f                // 1/16

// ---------------------------------------------------------------------------
// Scratch (no cudaMalloc allowed)
// ---------------------------------------------------------------------------
__device__ float g_q [NROWS*DIMN];
__device__ float g_k [NROWS*DIMN];
__device__ float g_v [NROWS*DIMN];
__device__ float g_g [NROWS*DIMN];
__device__ float g_gk[NROWS*DIMN];
// chunked-GLA scratch
__device__ float g_qg[NROWS*DIMN];
__device__ float g_kd[NROWS*DIMN];
__device__ float g_kv[16*NC*HKD*HKD];
__device__ float g_S [16*NC*HKD*HKD];
__device__ float g_dc[16*NC*HKD];
// bf16 split-precision operands
__device__ __nv_bfloat16 g_xhi [NROWS*DIMN];
__device__ __nv_bfloat16 g_xlo [NROWS*DIMN];
__device__ __nv_bfloat16 g_onhi[NROWS*DIMN];
__device__ __nv_bfloat16 g_onlo[NROWS*DIMN];
__device__ __nv_bfloat16 g_Whi [5*DIMN*DIMN];   // transposed: [n][k]
__device__ __nv_bfloat16 g_Wlo [5*DIMN*DIMN];

// ---------------------------------------------------------------------------
// PTX helpers (all non-'a'-gated: cp.async / ldmatrix / mma.sync)
// ---------------------------------------------------------------------------
__device__ __forceinline__ uint32_t smem_u32(const void* p) {
    uint32_t a;
    asm("{ .reg .u64 t; cvta.to.shared.u64 t, %1; cvt.u32.u64 %0, t; }"
        : "=r"(a) : "l"(p));
    return a;
}
__device__ __forceinline__ void cp16(uint32_t dst, const void* src) {
    asm volatile("cp.async.cg.shared.global [%0], [%1], 16;"
                 :: "r"(dst), "l"(src) : "memory");
}
__device__ __forceinline__ void cp_commit() {
    asm volatile("cp.async.commit_group;" ::: "memory");
}
__device__ __forceinline__ void ldsm4(uint32_t& r0, uint32_t& r1,
                                      uint32_t& r2, uint32_t& r3, uint32_t a) {
    asm volatile("ldmatrix.sync.aligned.m8n8.x4.shared.b16 {%0,%1,%2,%3}, [%4];"
                 : "=r"(r0), "=r"(r1), "=r"(r2), "=r"(r3) : "r"(a));
}
__device__ __forceinline__ void mma16816(float* c, const uint32_t* a,
                                         const uint32_t* b) {
    asm volatile("mma.sync.aligned.m16n8k16.row.col.f32.bf16.bf16.f32 "
        "{%0,%1,%2,%3}, {%4,%5,%6,%7}, {%8,%9}, {%0,%1,%2,%3};"
        : "+f"(c[0]), "+f"(c[1]), "+f"(c[2]), "+f"(c[3])
        : "r"(a[0]), "r"(a[1]), "r"(a[2]), "r"(a[3]), "r"(b[0]), "r"(b[1]));
}

// ---------------------------------------------------------------------------
// bf16 split conversions
// ---------------------------------------------------------------------------
__device__ __forceinline__ void split_bf16(float x, __nv_bfloat16& h, __nv_bfloat16& l) {
    h = __float2bfloat16(x);
    l = __float2bfloat16(x - __bfloat162float(h));
}

// NOTE: device globals are referenced INSIDE kernels only (host-side symbol
// would be the ATS shadow -> silent wrong-memory writes).
__global__ __launch_bounds__(256) void conv_x_kernel(const float* __restrict__ x)
{
    int i = blockIdx.x * 256 + threadIdx.x;       // float4 index
    float4 v = ((const float4*)x)[i];
    __nv_bfloat16 h[4], l[4];
    split_bf16(v.x, h[0], l[0]); split_bf16(v.y, h[1], l[1]);
    split_bf16(v.z, h[2], l[2]); split_bf16(v.w, h[3], l[3]);
    __nv_bfloat162* ph = (__nv_bfloat162*)g_xhi;
    __nv_bfloat162* pl = (__nv_bfloat162*)g_xlo;
    ph[i*2]   = __nv_bfloat162(h[0], h[1]);
    ph[i*2+1] = __nv_bfloat162(h[2], h[3]);
    pl[i*2]   = __nv_bfloat162(l[0], l[1]);
    pl[i*2+1] = __nv_bfloat162(l[2], l[3]);
}

// W fp32 [k][n] -> transposed bf16 hi/lo [n][k] (5 weights via z)
__global__ __launch_bounds__(256) void conv_w_kernel(
    const float* __restrict__ Wq, const float* __restrict__ Wk,
    const float* __restrict__ Wv, const float* __restrict__ Wg,
    const float* __restrict__ Wo)
{
    const float* Ws[5] = {Wq, Wk, Wv, Wg, Wo};
    const float* W = Ws[blockIdx.z];
    __nv_bfloat16* Dhi = g_Whi + (size_t)blockIdx.z * DIMN * DIMN;
    __nv_bfloat16* Dlo = g_Wlo + (size_t)blockIdx.z * DIMN * DIMN;

    __shared__ float s[32][33];
    int tx = threadIdx.x & 31, ty = threadIdx.x >> 5;   // 32 x 8
    int kt = blockIdx.y * 32, nt = blockIdx.x * 32;
#pragma unroll
    for (int j = 0; j < 4; j++)
        s[ty + j*8][tx] = W[(kt + ty + j*8) * DIMN + nt + tx];
    __syncthreads();
#pragma unroll
    for (int j = 0; j < 4; j++) {
        int n = nt + ty + j*8, k = kt + tx;
        float w = s[tx][ty + j*8];
        __nv_bfloat16 h, l; split_bf16(w, h, l);
        Dhi[(size_t)n * DIMN + k] = h;
        Dlo[(size_t)n * DIMN + k] = l;
    }
}

// ---------------------------------------------------------------------------
// HMMA split-3 GEMM v4 (round-10 proven): block 128x64, BK=32, 8 warps,
// 3-stage cp.async + register fragment double-buffering, 1 sync per K-step.
// ---------------------------------------------------------------------------
#define STG_BYTES 24576
#define OFF_AHI 0
#define OFF_ALO 8192
#define OFF_BHI 16384
#define OFF_BLO 20480
#define SMEM_GEMM (3*STG_BYTES)     // 72 KB (opt-in attr; 2 blocks/SM)

__device__ __forceinline__ uint32_t sw_addr(uint32_t region, int row, int chunk) {
    return region + row * 64 + ((chunk ^ ((row >> 1) & 3)) << 4);
}

__device__ __forceinline__ void load_stage(
    uint32_t sb, int s,
    const __nv_bfloat16* __restrict__ Ahi, const __nv_bfloat16* __restrict__ Alo,
    const __nv_bfloat16* __restrict__ Bhi, const __nv_bfloat16* __restrict__ Blo,
    int m0, int n0, int k0, int tid)
{
    uint32_t st = sb + s * STG_BYTES;
#pragma unroll
    for (int i = 0; i < 2; i++) {
        int idx = tid + (i << 8);          // 0..511
        int row = idx >> 2, c = idx & 3;
        const size_t go = (size_t)(m0 + row) * DIMN + k0 + c * 8;
        cp16(sw_addr(st + OFF_AHI, row, c), Ahi + go);
        cp16(sw_addr(st + OFF_ALO, row, c), Alo + go);
    }
    {
        int row = tid >> 2, c = tid & 3;   // 64 rows x 4 chunks
        const size_t go = (size_t)(n0 + row) * DIMN + k0 + c * 8;
        cp16(sw_addr(st + OFF_BHI, row, c), Bhi + go);
        cp16(sw_addr(st + OFF_BLO, row, c), Blo + go);
    }
    cp_commit();
}

struct FragSet {
    uint32_t ahi[2][4], alo[2][4];
    uint32_t bhi[4][2], blo[4][2];
};

__device__ __forceinline__ void ld_frags(FragSet& f, uint32_t st, int ch,
                                         int wm0, int wn0, int lr)
{
#pragma unroll
    for (int mt = 0; mt < 2; mt++) {
        int row = wm0 + mt * 16 + lr;
        ldsm4(f.ahi[mt][0], f.ahi[mt][1], f.ahi[mt][2], f.ahi[mt][3],
              sw_addr(st + OFF_AHI, row, ch));
        ldsm4(f.alo[mt][0], f.alo[mt][1], f.alo[mt][2], f.alo[mt][3],
              sw_addr(st + OFF_ALO, row, ch));
    }
#pragma unroll
    for (int ng = 0; ng < 2; ng++) {
        int row = wn0 + ng * 16 + lr;
        uint32_t t0, t1, t2, t3;
        ldsm4(t0, t1, t2, t3, sw_addr(st + OFF_BHI, row, ch));
        f.bhi[ng*2][0] = t0; f.bhi[ng*2+1][0] = t1;
        f.bhi[ng*2][1] = t2; f.bhi[ng*2+1][1] = t3;
        ldsm4(t0, t1, t2, t3, sw_addr(st + OFF_BLO, row, ch));
        f.blo[ng*2][0] = t0; f.blo[ng*2+1][0] = t1;
        f.blo[ng*2][1] = t2; f.blo[ng*2+1][1] = t3;
    }
}

__device__ __forceinline__ void mma_set(float acc[2][4][4], const FragSet& f)
{
#pragma unroll
    for (int mt = 0; mt < 2; mt++)
#pragma unroll
        for (int nt = 0; nt < 4; nt++) {
            mma16816(acc[mt][nt], f.ahi[mt], f.bhi[nt]);
            mma16816(acc[mt][nt], f.ahi[mt], f.blo[nt]);
            mma16816(acc[mt][nt], f.alo[mt], f.bhi[nt]);
        }
}

__device__ __forceinline__ void gemm_body(
    const __nv_bfloat16* __restrict__ Ahi, const __nv_bfloat16* __restrict__ Alo,
    const __nv_bfloat16* __restrict__ Bhi, const __nv_bfloat16* __restrict__ Blo,
    float* __restrict__ C, float alpha, char* smem)
{
    const int tid  = threadIdx.x;
    const int wid  = tid >> 5;
    const int lane = tid & 31;
    const int m0 = blockIdx.y * 128;
    const int n0 = blockIdx.x * 64;
    const int wm0 = (wid & 3) * 32;     // warp m within block
    const int wn0 = (wid >> 2) * 32;    // warp n within block
    const uint32_t sb = smem_u32(smem);

    float acc[2][4][4];
#pragma unroll
    for (int mt = 0; mt < 2; mt++)
#pragma unroll
        for (int nt = 0; nt < 4; nt++)
#pragma unroll
            for (int i = 0; i < 4; i++) acc[mt][nt][i] = 0.f;

    load_stage(sb, 0, Ahi, Alo, Bhi, Blo, m0, n0, 0,  tid);
    load_stage(sb, 1, Ahi, Alo, Bhi, Blo, m0, n0, 32, tid);

    const int lr = lane & 15;
    const int lc = lane >> 4;

    asm volatile("cp.async.wait_group 1;" ::: "memory");
    __syncthreads();

    FragSet cur, nxt;
    int stage = 0;
    uint32_t st = sb;
    ld_frags(cur, st, lc, wm0, wn0, lr);          // (kt=0, ks=0)

    for (int kt = 0; kt < 32; kt++) {
        ld_frags(nxt, st, 2 + lc, wm0, wn0, lr);  // (kt, ks=1)
        mma_set(acc, cur);                        // covers nxt's ldsm latency
        if (kt < 31) {
            if (kt < 30) {
                int ns = stage + 2; if (ns >= 3) ns -= 3;
                load_stage(sb, ns, Ahi, Alo, Bhi, Blo, m0, n0, (kt + 2) * 32, tid);
                asm volatile("cp.async.wait_group 1;" ::: "memory");
            } else {
                asm volatile("cp.async.wait_group 0;" ::: "memory");
            }
            __syncthreads();
            stage++; if (stage == 3) stage = 0;
            st = sb + stage * STG_BYTES;
            ld_frags(cur, st, lc, wm0, wn0, lr);  // (kt+1, ks=0)
        }
        mma_set(acc, nxt);                        // covers cur's ldsm latency
    }

    const int er = lane >> 2;
    const int ec = (lane & 3) << 1;
#pragma unroll
    for (int mt = 0; mt < 2; mt++)
#pragma unroll
        for (int nt = 0; nt < 4; nt++) {
            int row = m0 + wm0 + mt * 16 + er;
            int col = n0 + wn0 + nt * 8 + ec;
            float2 v0 = make_float2(acc[mt][nt][0] * alpha, acc[mt][nt][1] * alpha);
            float2 v1 = make_float2(acc[mt][nt][2] * alpha, acc[mt][nt][3] * alpha);
            *(float2*)(C + (size_t)row * DIMN + col)       = v0;
            *(float2*)(C + (size_t)(row + 8) * DIMN + col) = v1;
        }
}

__global__ __launch_bounds__(256, 2) void gemm4_kernel()
{
    extern __shared__ char smem[];
    const int z = blockIdx.z;
    const __nv_bfloat16* Bhi = g_Whi + (size_t)z * DIMN * DIMN;
    const __nv_bfloat16* Blo = g_Wlo + (size_t)z * DIMN * DIMN;
    float* outs[4] = {g_q, g_k, g_v, g_g};
    float alpha = (z == 0) ? QSCALE : 1.f;
    gemm_body(g_xhi, g_xlo, Bhi, Blo, outs[z], alpha, smem);
}

__global__ __launch_bounds__(256, 2) void gemmo_kernel(float* __restrict__ out)
{
    extern __shared__ char smem[];
    gemm_body(g_onhi, g_onlo, g_Whi + (size_t)4 * DIMN * DIMN,
              g_Wlo + (size_t)4 * DIMN * DIMN, out, 1.f, smem);
}

// ---------------------------------------------------------------------------
// Fused low-rank gate path, 16 rows per block (64 blocks).
// ---------------------------------------------------------------------------
__global__ __launch_bounds__(256) void lowrank_gk_kernel(
    const float* __restrict__ x, const float* __restrict__ Wgk1,
    const float* __restrict__ Wgk2, const float* __restrict__ bgk2)
{
    const int m0  = blockIdx.x * 16;
    const int tid = threadIdx.x;

    __shared__ float sX[16][64];
    __shared__ float sPart[16][16][16];   // [kk][r][c]
    __shared__ float sT1[16][16];         // [r][c]

    const int kk = tid >> 4;   // 0..15
    const int cc = tid & 15;   // 0..15

    float acc16[16];
#pragma unroll
    for (int r = 0; r < 16; r++) acc16[r] = 0.f;

    for (int kc = 0; kc < 16; kc++) {
        {
            int row = tid >> 4, c4 = (tid & 15) << 2;
            *(float4*)&sX[row][c4] =
                *(const float4*)(x + (size_t)(m0 + row) * DIMN + kc * 64 + c4);
        }
        __syncthreads();
#pragma unroll
        for (int i = 0; i < 4; i++) {
            int k = kk * 4 + i;
            float w1 = Wgk1[(kc * 64 + k) * 16 + cc];
#pragma unroll
            for (int r = 0; r < 16; r++)
                acc16[r] = fmaf(sX[r][k], w1, acc16[r]);
        }
        __syncthreads();
    }
#pragma unroll
    for (int r = 0; r < 16; r++) sPart[kk][r][cc] = acc16[r];
    __syncthreads();

    {
        int rr = tid >> 4;
        float s = 0.f;
#pragma unroll
        for (int j = 0; j < 16; j++) s += sPart[j][rr][cc];
        sT1[rr][cc] = s;
    }
    __syncthreads();

#pragma unroll
    for (int u = 0; u < 4; u++) {
        int n = u * 256 + tid;
        float w2[16];
#pragma unroll
        for (int j = 0; j < 16; j++) w2[j] = Wgk2[j * DIMN + n];
        float bias = bgk2[n];
#pragma unroll
        for (int r = 0; r < 16; r++) {
            float a = bias;
#pragma unroll
            for (int j = 0; j < 16; j++)
                a = fmaf(sT1[r][j], w2[j], a);
            float ls = fminf(a, 0.f) - log1pf(__expf(-fabsf(a)));
            g_gk[(size_t)(m0 + r) * DIMN + n] = ls * GNORM;
        }
    }
}

// ---------------------------------------------------------------------------
// Chunked GLA
// ---------------------------------------------------------------------------
__device__ __forceinline__ int row_off(int b, int h, int t)
{
    return (((b * TT + t) * HH + h) << 7);
}

// Fused prep + chunk_kv, v-split into 2 halves: 256 blocks (bhc x vhalf).
// Gate prep computed by both halves (k~ is k-indexed, fully needed); global
// qg/kd/dc writes only from half 0. KV matmul covers 64 v-columns per block.
__global__ __launch_bounds__(512) void prep_kv_kernel()
{
    const int bid = blockIdx.x;
    const int bhc = bid >> 1, vh = bid & 1;
    const int bh  = bhc >> 3, c0 = bhc & 7;
    const int b   = bh >> 3,  h  = bh & 7;
    const int tid = threadIdx.x;
    const int ch  = tid & 127;
    const int tg  = tid >> 7;          // 0..3, each handles 16 t's
    const int tb  = c0 * CH + tg * 16;

    __shared__ float gsum[4][128];
    __shared__ float sK[64][128];      // k~ [t][channel], 32 KB
    __shared__ float sV[16][64];

    float loc[16];
    {
        float a = 0.f;
#pragma unroll
        for (int s = 0; s < 16; s++) {
            loc[s] = g_gk[row_off(b, h, tb + s) + ch];
            a += loc[s];
        }
        gsum[tg][ch] = a;
    }
    __syncthreads();
    {
        float off = 0.f;
#pragma unroll
        for (int g = 0; g < 4; g++)
            if (g < tg) off += gsum[g][ch];
        float tot = gsum[0][ch] + gsum[1][ch] + gsum[2][ch] + gsum[3][ch];
        float bacc = off;
#pragma unroll 4
        for (int s = 0; s < 16; s++) {
            bacc += loc[s];
            int r = row_off(b, h, tb + s) + ch;
            float q = g_q[r], k = g_k[r];
            if (vh == 0) {
                g_qg[r] = q * __expf(bacc);
                g_kd[r] = k * __expf(-bacc);
            }
            sK[tg * 16 + s][ch] = k * __expf(tot - bacc);
        }
        if (vh == 0 && tg == 0) g_dc[bhc * 128 + ch] = __expf(tot);
    }
    __syncthreads();

    // KV matmul: contraction over s=64, output [k 128][v 64], 4x4 per thread
    const int tr  = tid >> 4, tc = tid & 15;   // tr 0..31
    const int kr0 = tr << 2, vc0 = tc << 2;
    const int tbase = c0 * CH;
    const int vbase = vh * 64;

    float acc[4][4];
#pragma unroll
    for (int i = 0; i < 4; i++)
#pragma unroll
        for (int j = 0; j < 4; j++) acc[i][j] = 0.f;

    for (int st = 0; st < 4; st++) {
        if (tid < 256) {
            int sr = tid >> 4;
            int sc = (tid & 15) << 2;
            int r  = row_off(b, h, tbase + st * 16 + sr) + vbase + sc;
            *(float4*)&sV[sr][sc] = *(const float4*)(g_v + r);
        }
        __syncthreads();
#pragma unroll
        for (int ss = 0; ss < 16; ss++) {
            int s = st * 16 + ss;
            float4 k4 = *(const float4*)&sK[s][kr0];
            float4 v4 = *(const float4*)&sV[ss][vc0];
            float kr[4] = {k4.x,k4.y,k4.z,k4.w};
            float vr[4] = {v4.x,v4.y,v4.z,v4.w};
#pragma unroll
            for (int i = 0; i < 4; i++)
#pragma unroll
                for (int j = 0; j < 4; j++)
                    acc[i][j] = fmaf(kr[i], vr[j], acc[i][j]);
        }
        __syncthreads();
    }

    float* dst = g_kv + (size_t)bhc * 16384 + vbase;
#pragma unroll
    for (int i = 0; i < 4; i++)
        *(float4*)(dst + (kr0 + i) * 128 + vc0) =
            make_float4(acc[i][0], acc[i][1], acc[i][2], acc[i][3]);
}

// state scan v2: 256 blocks (bh x 16 v-groups), 1 float4/thread, prefetched.
__global__ __launch_bounds__(256) void state_scan_kernel()
{
    const int bh = blockIdx.x >> 4;
    const int vg = blockIdx.x & 15;
    const int tid = threadIdx.x;
    const int k  = tid >> 1;
    const int v0 = vg * 8 + (tid & 1) * 4;

    const size_t slab = (size_t)bh * NC * 16384 + (size_t)k * 128 + v0;
    const int dbase = bh * NC * 128 + k;

    float4 S = make_float4(0.f, 0.f, 0.f, 0.f);
    float4 kv = *(const float4*)(g_kv + slab);
    float  d  = g_dc[dbase];

    for (int c = 0; c < NC; c++) {
        *(float4*)(g_S + slab + (size_t)c * 16384) = S;
        S.x = fmaf(S.x, d, kv.x); S.y = fmaf(S.y, d, kv.y);
        S.z = fmaf(S.z, d, kv.z); S.w = fmaf(S.w, d, kv.w);
        if (c < NC - 1) {
            kv = *(const float4*)(g_kv + slab + (size_t)(c + 1) * 16384);
            d  = g_dc[dbase + (c + 1) * 128];
        }
    }
}

// chunk_out: o = q~ @ S_c + tril(q~ @ k^^T) @ V, fused gated RMSNorm,
// writes bf16 hi/lo splits directly (feeds gemmo).
__global__ __launch_bounds__(256) void chunk_out_kernel(
    const float* __restrict__ g_norm_w)
{
    const int bhc = blockIdx.x;
    const int bh  = bhc >> 3, c0 = bhc & 7;
    const int b   = bh >> 3,  h  = bh & 7;
    const int tid = threadIdx.x;
    const int tr  = tid >> 4, tc = tid & 15;
    const int t0  = tr << 2;
    const int v0  = tc << 3;
    const int tbase = c0 * CH;

    __shared__ float sQ [16][68];
    __shared__ float sKd[16][68];
    __shared__ float sS [16][128];
    __shared__ float sA [64][68];
    __shared__ float sV [16][128];

    float o[4][8];
    float a2[4][4];
#pragma unroll
    for (int i = 0; i < 4; i++) {
#pragma unroll
        for (int j = 0; j < 8; j++) o[i][j] = 0.f;
#pragma unroll
        for (int j = 0; j < 4; j++) a2[i][j] = 0.f;
    }

    const size_t Sbase = (size_t)bhc * 16384;

    for (int k0 = 0; k0 < 128; k0 += 16) {
        {
            int tt = tid >> 2;
            int c4 = (tid & 3) << 2;
            int r  = row_off(b, h, tbase + tt) + k0 + c4;
            float4 qv = *(const float4*)(g_qg + r);
            sQ[c4+0][tt] = qv.x; sQ[c4+1][tt] = qv.y;
            sQ[c4+2][tt] = qv.z; sQ[c4+3][tt] = qv.w;
            float4 kv = *(const float4*)(g_kd + r);
            sKd[c4+0][tt] = kv.x; sKd[c4+1][tt] = kv.y;
            sKd[c4+2][tt] = kv.z; sKd[c4+3][tt] = kv.w;
        }
#pragma unroll
        for (int u = 0; u < 2; u++) {
            int f  = tid + (u << 8);
            int sr = f >> 5;
            int sc = (f & 31) << 2;
            *(float4*)&sS[sr][sc] =
                *(const float4*)(g_S + Sbase + (k0 + sr) * 128 + sc);
        }
        __syncthreads();

#pragma unroll
        for (int kk = 0; kk < 16; kk++) {
            float4 q4  = *(const float4*)&sQ[kk][t0];
            float4 s0  = *(const float4*)&sS[kk][v0];
            float4 s1  = *(const float4*)&sS[kk][v0 + 4];
            float4 kd4 = *(const float4*)&sKd[kk][tc << 2];
            float qr[4] = {q4.x, q4.y, q4.z, q4.w};
            float sr_[8] = {s0.x,s0.y,s0.z,s0.w,s1.x,s1.y,s1.z,s1.w};
            float kr[4] = {kd4.x,kd4.y,kd4.z,kd4.w};
#pragma unroll
            for (int i = 0; i < 4; i++) {
#pragma unroll
                for (int j = 0; j < 8; j++)
                    o[i][j] = fmaf(qr[i], sr_[j], o[i][j]);
#pragma unroll
                for (int j = 0; j < 4; j++)
                    a2[i][j] = fmaf(qr[i], kr[j], a2[i][j]);
            }
        }
        __syncthreads();
    }

#pragma unroll
    for (int i = 0; i < 4; i++) {
        int t = t0 + i;
#pragma unroll
        for (int j = 0; j < 4; j++) {
            int s = (tc << 2) + j;
            sA[t][s] = (s <= t) ? a2[i][j] : 0.f;
        }
    }
    __syncthreads();

    for (int st = 0; st < 4; st++) {
#pragma unroll
        for (int u = 0; u < 2; u++) {
            int f  = tid + (u << 8);
            int sr = f >> 5;
            int sc = (f & 31) << 2;
            int r  = row_off(b, h, tbase + st * 16 + sr) + sc;
            *(float4*)&sV[sr][sc] = *(const float4*)(g_v + r);
        }
        __syncthreads();
#pragma unroll
        for (int ss = 0; ss < 16; ss++) {
            int s = st * 16 + ss;
            float a[4];
#pragma unroll
            for (int i = 0; i < 4; i++) a[i] = sA[t0 + i][s];
            float4 vv0 = *(const float4*)&sV[ss][v0];
            float4 vv1 = *(const float4*)&sV[ss][v0 + 4];
            float vr[8] = {vv0.x,vv0.y,vv0.z,vv0.w,vv1.x,vv1.y,vv1.z,vv1.w};
#pragma unroll
            for (int i = 0; i < 4; i++)
#pragma unroll
                for (int j = 0; j < 8; j++)
                    o[i][j] = fmaf(a[i], vr[j], o[i][j]);
        }
        __syncthreads();
    }

    float4 w0 = *(const float4*)(g_norm_w + v0);
    float4 w1 = *(const float4*)(g_norm_w + v0 + 4);
    float wr[8] = {w0.x,w0.y,w0.z,w0.w,w1.x,w1.y,w1.z,w1.w};

#pragma unroll
    for (int i = 0; i < 4; i++) {
        float ss = 0.f;
#pragma unroll
        for (int j = 0; j < 8; j++) ss = fmaf(o[i][j], o[i][j], ss);
#pragma unroll
        for (int off = 1; off < 16; off <<= 1)
            ss += __shfl_xor_sync(0xffffffffu, ss, off);
        float rms = rsqrtf(ss * (1.f / 128.f) + 1e-5f);

        int r = row_off(b, h, tbase + t0 + i);
        float4 gg0 = *(const float4*)(g_g + r + v0);
        float4 gg1 = *(const float4*)(g_g + r + v0 + 4);
        float gr[8] = {gg0.x,gg0.y,gg0.z,gg0.w,gg1.x,gg1.y,gg1.z,gg1.w};

        union { __nv_bfloat16 h[8]; uint4 u; } hh;
        union { __nv_bfloat16 h[8]; uint4 u; } ll;
#pragma unroll
        for (int j = 0; j < 8; j++) {
            float gvv = gr[j];
            float sw  = gvv / (1.f + __expf(-gvv));
            float on  = o[i][j] * rms * wr[j] * sw;
            split_bf16(on, hh.h[j], ll.h[j]);
        }
        *(uint4*)&g_onhi[r + v0] = hh.u;
        *(uint4*)&g_onlo[r + v0] = ll.u;
    }
}

// ---------------------------------------------------------------------------
extern "C" void kernel_launch(void* const* d_in, const int* in_sizes, int n_in,
                              void* d_out, int out_size)
{
    const float* x        = (const float*)d_in[0];
    const float* Wq       = (const float*)d_in[1];
    const float* Wk       = (const float*)d_in[2];
    const float* Wv       = (const float*)d_in[3];
    const float* Wg       = (const float*)d_in[4];
    const float* Wgk1     = (const float*)d_in[5];
    const float* Wgk2     = (const float*)d_in[6];
    const float* bgk2     = (const float*)d_in[7];
    const float* g_norm_w = (const float*)d_in[8];
    const float* Wo       = (const float*)d_in[9];
    float* out = (float*)d_out;

    // Host-side attribute set; executed during capture, not a graph node.
    cudaFuncSetAttribute(gemm4_kernel,
        cudaFuncAttributeMaxDynamicSharedMemorySize, SMEM_GEMM);
    cudaFuncSetAttribute(gemmo_kernel,
        cudaFuncAttributeMaxDynamicSharedMemorySize, SMEM_GEMM);

    conv_w_kernel<<<dim3(32, 32, 5), dim3(256)>>>(Wq, Wk, Wv, Wg, Wo);
    conv_x_kernel<<<1024, 256>>>(x);
    lowrank_gk_kernel<<<64, 256>>>(x, Wgk1, Wgk2, bgk2);
    gemm4_kernel<<<dim3(16, 8, 4), 256, SMEM_GEMM>>>();
    prep_kv_kernel<<<256, 512>>>();
    state_scan_kernel<<<256, 256>>>();
    chunk_out_kernel<<<128, 256>>>(g_norm_w);
    gemmo_kernel<<<dim3(16, 8), 256, SMEM_GEMM>>>(out);
}